// round 16
// baseline (speedup 1.0000x reference)
#include <cuda_runtime.h>
#include <cuda_fp16.h>
#include <cstdint>
#include <cstddef>

#define DD 512
#define NNODE 100000
#define EMAX 1000000
typedef __half fp16;

// ---- static device scratch (allocation-free rule) ----
__device__ fp16  g_h0[NNODE * DD];      // fp16(lrelu(x0))
__device__ fp16  g_h1[NNODE * DD];
__device__ fp16  g_s0[NNODE * DD];      // fp16(lrelu(o0))
__device__ fp16  g_s1[NNODE * DD];
__device__ fp16  g_agga[NNODE * DD];    // agg for dst type 1
__device__ fp16  g_aggb[NNODE * DD];    // agg for dst type 0
__device__ fp16  g_Wph[8 * DD * DD];    // precombined fp16 weights
__device__ float g_bp[4 * DD];
__device__ int   g_csr01[EMAX];
__device__ int   g_csr10[EMAX];
__device__ int   g_rs01[NNODE + 1];
__device__ int   g_rs10[NNODE + 1];
__device__ int   g_cnt0[NNODE];
__device__ int   g_cnt1[NNODE];
__device__ int   g_part0[NNODE];
__device__ int   g_part1[NNODE];
__device__ int   g_bsum[256];
__device__ int   g_cur0[NNODE];
__device__ int   g_cur1[NNODE];

// ================= helpers =================
__device__ __forceinline__ float4 lrelu4(float4 v) {
    v.x = v.x > 0.f ? v.x : 0.01f * v.x;
    v.y = v.y > 0.f ? v.y : 0.01f * v.y;
    v.z = v.z > 0.f ? v.z : 0.01f * v.z;
    v.w = v.w > 0.f ? v.w : 0.01f * v.w;
    return v;
}
__device__ __forceinline__ uint2 pack4h(float4 v) {
    __half2 a = __floats2half2_rn(v.x, v.y);
    __half2 b = __floats2half2_rn(v.z, v.w);
    uint2 r;
    r.x = *(uint32_t*)&a;
    r.y = *(uint32_t*)&b;
    return r;
}

// ================= elementwise: lrelu -> fp16, both tensors in one launch =========
__global__ void hhalf2_k(const float4* __restrict__ inA, uint2* __restrict__ outA, int n4A,
                         const float4* __restrict__ inB, uint2* __restrict__ outB, int n4B) {
    int i = blockIdx.x * blockDim.x + threadIdx.x;
    if (i < n4A) {
        outA[i] = pack4h(lrelu4(inA[i]));
    } else {
        int j = i - n4A;
        if (j < n4B) outB[j] = pack4h(lrelu4(inB[j]));
    }
}

// ================= CSR build (batched over both edge types) =================
__global__ void hist2_k(const int* __restrict__ eiA, int EA, int* __restrict__ cntA,
                        const int* __restrict__ eiB, int EB, int* __restrict__ cntB) {
    const int* ei = blockIdx.y ? eiB : eiA;
    int* cnt = blockIdx.y ? cntB : cntA;
    int E = blockIdx.y ? EB : EA;
    int e = blockIdx.x * blockDim.x + threadIdx.x;
    if (e < E) atomicAdd(&cnt[ei[E + e]], 1);
}
__global__ void scan1_k(const int* __restrict__ cntA, const int* __restrict__ cntB,
                        int NA, int NB, int* __restrict__ partA, int* __restrict__ partB,
                        int* __restrict__ bsum) {
    const int* cnt = blockIdx.y ? cntB : cntA;
    int* part = blockIdx.y ? partB : partA;
    int N = blockIdx.y ? NB : NA;
    int* bs = bsum + blockIdx.y * 128;
    __shared__ int sh[1024];
    int t = threadIdx.x;
    int i = blockIdx.x * 1024 + t;
    sh[t] = (i < N) ? cnt[i] : 0;
    __syncthreads();
    for (int off = 1; off < 1024; off <<= 1) {
        int v = (t >= off) ? sh[t - off] : 0;
        __syncthreads();
        sh[t] += v;
        __syncthreads();
    }
    if (i < N) part[i] = sh[t];
    if (t == 1023) bs[blockIdx.x] = sh[1023];
}
__global__ void scan2_k(int* __restrict__ bsum, int nb) {
    __shared__ int sh[128];
    int* bs = bsum + blockIdx.y * 128;
    int t = threadIdx.x;
    sh[t] = (t < nb) ? bs[t] : 0;
    __syncthreads();
    for (int off = 1; off < 128; off <<= 1) {
        int v = (t >= off) ? sh[t - off] : 0;
        __syncthreads();
        sh[t] += v;
        __syncthreads();
    }
    if (t < nb) bs[t] = sh[t];
}
__global__ void scan3_k(const int* __restrict__ partA, const int* __restrict__ partB,
                        const int* __restrict__ bsum, int* __restrict__ rsA,
                        int* __restrict__ rsB, int NA, int NB) {
    const int* part = blockIdx.y ? partB : partA;
    int* rs = blockIdx.y ? rsB : rsA;
    int N = blockIdx.y ? NB : NA;
    const int* bs = bsum + blockIdx.y * 128;
    int i = blockIdx.x * blockDim.x + threadIdx.x;
    if (i < N) {
        int b = i >> 10;
        int off = (b > 0) ? bs[b - 1] : 0;
        rs[i + 1] = part[i] + off;
    }
    if (i == 0) rs[0] = 0;
}
__global__ void fill2_k(const int* __restrict__ eiA, int EA, const int* __restrict__ rsA,
                        int* __restrict__ curA, int* __restrict__ csrA,
                        const int* __restrict__ eiB, int EB, const int* __restrict__ rsB,
                        int* __restrict__ curB, int* __restrict__ csrB) {
    const int* ei = blockIdx.y ? eiB : eiA;
    const int* rs = blockIdx.y ? rsB : rsA;
    int* cur = blockIdx.y ? curB : curA;
    int* csr = blockIdx.y ? csrB : csrA;
    int E = blockIdx.y ? EB : EA;
    int e = blockIdx.x * blockDim.x + threadIdx.x;
    if (e >= E) return;
    int s = ei[e], d = ei[E + e];
    int pos = atomicAdd(&cur[d], 1);
    csr[rs[d] + pos] = s;
}

// ================= fused dual CSR gather over fp16 features -> fp16 mean ============
__global__ void gather2h_k(const fp16* __restrict__ fA, const int* __restrict__ csrA,
                           const int* __restrict__ rsA, int NA, uint4* __restrict__ aggA,
                           const fp16* __restrict__ fB, const int* __restrict__ csrB,
                           const int* __restrict__ rsB, int NB, uint4* __restrict__ aggB) {
    int w = (blockIdx.x * blockDim.x + threadIdx.x) >> 5;
    if (w >= NA + NB) return;
    int lane = threadIdx.x & 31;
    const fp16* feat;
    const int* csr;
    const int* rs;
    uint4* agg;
    int node;
    if (w < NA) { feat = fA; csr = csrA; rs = rsA; agg = aggA; node = w; }
    else        { feat = fB; csr = csrB; rs = rsB; agg = aggB; node = w - NA; }
    int beg = rs[node], end = rs[node + 1];
    float a[16];
#pragma unroll
    for (int i = 0; i < 16; i++) a[i] = 0.f;
    int e = beg;
    for (; e + 1 < end; e += 2) {
        const uint4* p = (const uint4*)(feat + (size_t)csr[e] * DD);
        const uint4* q = (const uint4*)(feat + (size_t)csr[e + 1] * DD);
        uint4 v0 = p[lane], v1 = p[lane + 32];
        uint4 w0 = q[lane], w1 = q[lane + 32];
        const uint32_t *u0 = &v0.x, *u1 = &v1.x, *t0 = &w0.x, *t1 = &w1.x;
#pragma unroll
        for (int j = 0; j < 4; j++) {
            float2 f0 = __half22float2(*(const __half2*)&u0[j]);
            float2 f1 = __half22float2(*(const __half2*)&u1[j]);
            float2 g0 = __half22float2(*(const __half2*)&t0[j]);
            float2 g1 = __half22float2(*(const __half2*)&t1[j]);
            a[2 * j] += f0.x + g0.x;         a[2 * j + 1] += f0.y + g0.y;
            a[8 + 2 * j] += f1.x + g1.x;     a[8 + 2 * j + 1] += f1.y + g1.y;
        }
    }
    if (e < end) {
        const uint4* p = (const uint4*)(feat + (size_t)csr[e] * DD);
        uint4 v0 = p[lane], v1 = p[lane + 32];
        const uint32_t *u0 = &v0.x, *u1 = &v1.x;
#pragma unroll
        for (int j = 0; j < 4; j++) {
            float2 f0 = __half22float2(*(const __half2*)&u0[j]);
            float2 f1 = __half22float2(*(const __half2*)&u1[j]);
            a[2 * j] += f0.x;     a[2 * j + 1] += f0.y;
            a[8 + 2 * j] += f1.x; a[8 + 2 * j + 1] += f1.y;
        }
    }
    int deg = end - beg;
    float sc = 1.f / (float)(deg > 1 ? deg : 1);
    uint4 o0, o1;
    uint32_t* q0 = &o0.x;
    uint32_t* q1 = &o1.x;
#pragma unroll
    for (int j = 0; j < 4; j++) {
        __half2 h0 = __floats2half2_rn(a[2 * j] * sc, a[2 * j + 1] * sc);
        __half2 h1 = __floats2half2_rn(a[8 + 2 * j] * sc, a[8 + 2 * j + 1] * sc);
        q0[j] = *(uint32_t*)&h0;
        q1[j] = *(uint32_t*)&h1;
    }
    size_t rb = (size_t)node * (DD / 8);
    agg[rb + lane] = o0;
    agg[rb + lane + 32] = o1;
}

// ================= bias precombination (4 sets, one launch) =================
struct BCPtrs { const float *bn[4], *bs[4], *bu[4], *Wu[4]; };

__global__ void biascomb_k(BCPtrs p, float* __restrict__ bp) {
    int s = blockIdx.y;
    int j = blockIdx.x * blockDim.x + threadIdx.x;
    if (j >= DD) return;
    const float* WuT = p.Wu[s];
    const float* WuB = p.Wu[s] + DD * DD;
    const float* bn = p.bn[s];
    const float* bs = p.bs[s];
    float acc = p.bu[s][j];
    for (int k = 0; k < DD; k++)
        acc += bn[k] * WuT[k * DD + j] + bs[k] * WuB[k * DD + j];
    bp[s * DD + j] = acc;
}

// ================= batched fp32 512^3 precombine GEMM -> fp16 out =================
struct PrePtrs { const float* A[8]; const float* Bm[8]; fp16* C[8]; };

__global__ __launch_bounds__(256, 2) void gemm_pre_k(PrePtrs p) {
    const float* A = p.A[blockIdx.z];
    const float* W = p.Bm[blockIdx.z];
    fp16* C = p.C[blockIdx.z];
    __shared__ float As[16][128];
    __shared__ float Bs[16][128];
    const int tid = threadIdx.x;
    const int tx = tid & 15, ty = tid >> 4;
    const int row0 = blockIdx.y * 128, col0 = blockIdx.x * 128;
    float acc[8][8];
#pragma unroll
    for (int i = 0; i < 8; i++)
#pragma unroll
        for (int j = 0; j < 8; j++) acc[i][j] = 0.f;
    const int lm = tid >> 1, lk = (tid & 1) * 8;
    const int wk = tid >> 4, wc = (tid & 15) * 8;
    for (int kk = 0; kk < 512; kk += 16) {
        const float* pA = A + (size_t)(row0 + lm) * 512 + kk + lk;
        float4 a0 = *(const float4*)pA, a1 = *(const float4*)(pA + 4);
        const float* pW = W + (size_t)(kk + wk) * 512 + col0 + wc;
        float4 w0 = *(const float4*)pW, w1 = *(const float4*)(pW + 4);
        As[lk + 0][lm] = a0.x; As[lk + 1][lm] = a0.y;
        As[lk + 2][lm] = a0.z; As[lk + 3][lm] = a0.w;
        As[lk + 4][lm] = a1.x; As[lk + 5][lm] = a1.y;
        As[lk + 6][lm] = a1.z; As[lk + 7][lm] = a1.w;
        *(float4*)&Bs[wk][wc] = w0;
        *(float4*)&Bs[wk][wc + 4] = w1;
        __syncthreads();
#pragma unroll
        for (int k = 0; k < 16; k++) {
            float ra[8], rb[8];
            *(float4*)&ra[0] = *(const float4*)&As[k][ty * 8];
            *(float4*)&ra[4] = *(const float4*)&As[k][ty * 8 + 4];
            *(float4*)&rb[0] = *(const float4*)&Bs[k][tx * 8];
            *(float4*)&rb[4] = *(const float4*)&Bs[k][tx * 8 + 4];
#pragma unroll
            for (int i = 0; i < 8; i++)
#pragma unroll
                for (int j = 0; j < 8; j++) acc[i][j] += ra[i] * rb[j];
        }
        __syncthreads();
    }
#pragma unroll
    for (int i = 0; i < 8; i++) {
        fp16* cp = C + (size_t)(row0 + ty * 8 + i) * 512 + col0 + tx * 8;
        uint4 o;
        uint32_t* q = &o.x;
#pragma unroll
        for (int j = 0; j < 4; j++) {
            __half2 h = __floats2half2_rn(acc[i][2 * j], acc[i][2 * j + 1]);
            q[j] = *(uint32_t*)&h;
        }
        *(uint4*)cp = o;
    }
}

// ================= fp16 single-pass tensor-core GEMM, paired via blockIdx.z ==========
// C = A0@W0 + A1@W1 + bias.  All operands plain fp16, fp32 accum.
// 128x128 tile, K chunk 64, 3-stage cp.async ring, 2 CTAs/SM.

#define APAD 72                           // 64 + 8
#define BPAD 136                          // 128 + 8
#define A_T (128 * APAD)                  // 9216 elems
#define B_T (64 * BPAD)                   // 8704 elems
#define STG (A_T + B_T)                   // 17920 elems per stage
#define NSTAGE 3
#define GEMM_SMEM (NSTAGE * STG * 2)      // 107,520 bytes
#define NST 16                             // 2 phases * (512/64)

__device__ __forceinline__ void cp16(uint32_t s, const void* g, int p16) {
    asm volatile("cp.async.cg.shared.global [%0], [%1], 16, %2;\n"
                 :: "r"(s), "l"(g), "r"(p16));
}

#define LDSM4(R, addr) \
    asm volatile("ldmatrix.sync.aligned.m8n8.x4.shared.b16 {%0,%1,%2,%3},[%4];\n" \
        : "=r"((R)[0]), "=r"((R)[1]), "=r"((R)[2]), "=r"((R)[3]) : "r"(addr))

#define LDSM4T(r0, r1, r2, r3, addr) \
    asm volatile("ldmatrix.sync.aligned.m8n8.x4.trans.shared.b16 {%0,%1,%2,%3},[%4];\n" \
        : "=r"(r0), "=r"(r1), "=r"(r2), "=r"(r3) : "r"(addr))

#define MMA16816(D, Af, Bf) \
    asm volatile("mma.sync.aligned.m16n8k16.row.col.f32.f16.f16.f32 " \
        "{%0,%1,%2,%3},{%4,%5,%6,%7},{%8,%9},{%0,%1,%2,%3};\n" \
        : "+f"((D)[0]), "+f"((D)[1]), "+f"((D)[2]), "+f"((D)[3]) \
        : "r"((Af)[0]), "r"((Af)[1]), "r"((Af)[2]), "r"((Af)[3]), \
          "r"((Bf)[0]), "r"((Bf)[1]))

struct G2 {
    const fp16 *A0[2], *A1[2];
    const fp16 *W0[2], *W1[2];
    const float *bias[2];
    float *C[2];            // optional fp32 out (nullptr to skip)
    uint32_t *Split[2];     // optional fp16(lrelu(C)) out (nullptr to skip)
    int M[2];
};

__global__ __launch_bounds__(256, 2) void gemm_fp16_k(G2 g) {
    const int z = blockIdx.z;
    const fp16* A0 = g.A0[z];
    const fp16* A1 = g.A1[z];
    const fp16* W0 = g.W0[z];
    const fp16* W1 = g.W1[z];
    const float* bias = g.bias[z];
    float* C = g.C[z];
    uint32_t* Split = g.Split[z];
    const int M = g.M[z];

    extern __shared__ fp16 smdyn[];
    uint32_t smb = (uint32_t)__cvta_generic_to_shared(smdyn);
    const int tid = threadIdx.x;
    const int lane = tid & 31;
    const int wid = tid >> 5;
    const int warp_m = wid & 1, warp_n = wid >> 1;
    const int row0 = blockIdx.y * 128, col0 = blockIdx.x * 128;
    if (row0 >= M) return;

    float acc[16][4];
#pragma unroll
    for (int i = 0; i < 16; i++) { acc[i][0] = acc[i][1] = acc[i][2] = acc[i][3] = 0.f; }

    // loader mapping: A tile 128x64 (4 cp16/thread), B tile 64x128 (4 cp16/thread)
    const int arow = tid >> 1, ac0 = (tid & 1) * 32;
    const int brow = tid >> 2, bc0 = (tid & 3) * 32;
    const int agrow = row0 + arow;
    const int apred = (agrow < M) ? 16 : 0;
    const size_t aoff = (size_t)(agrow < M ? agrow : 0) * DD;

    auto issue = [&](int s) {
        const int ph = s >> 3;              // 0 = (A0,W0), 1 = (A1,W1)
        const int k0 = (s & 7) * 64;        // K chunk within phase (8 x 64 = 512)
        const int buf = s % NSTAGE;
        const fp16* A = ph ? A1 : A0;
        const fp16* W = ph ? W1 : W0;
        uint32_t base = smb + buf * (STG * 2);
        uint32_t sa = base + (arow * APAD + ac0) * 2;
        const fp16* ga = A + aoff + k0 + ac0;
        cp16(sa, ga, apred);
        cp16(sa + 16, ga + 8, apred);
        cp16(sa + 32, ga + 16, apred);
        cp16(sa + 48, ga + 24, apred);
        uint32_t sb = base + (A_T + brow * BPAD + bc0) * 2;
        const fp16* gb = W + (size_t)(k0 + brow) * DD + col0 + bc0;
        cp16(sb, gb, 16);
        cp16(sb + 16, gb + 8, 16);
        cp16(sb + 32, gb + 16, 16);
        cp16(sb + 48, gb + 24, 16);
        asm volatile("cp.async.commit_group;\n");
    };

    const int am = warp_m * 64 + (lane & 15);
    const int akoff = (lane >> 4) << 3;           // 0 or 8
    const int bk = lane & 15;
    const int bn = warp_n * 32 + ((lane & 16) ? 8 : 0);

    issue(0); issue(1); issue(2);

#pragma unroll 1
    for (int s = 0; s < NST; s++) {
        if (s < NST - 2)       asm volatile("cp.async.wait_group 2;\n" ::: "memory");
        else if (s == NST - 2) asm volatile("cp.async.wait_group 1;\n" ::: "memory");
        else                   asm volatile("cp.async.wait_group 0;\n" ::: "memory");
        __syncthreads();

        const int buf = s % NSTAGE;
        uint32_t base = smb + buf * (STG * 2);
        uint32_t Ab = base;
        uint32_t Bb = base + A_T * 2;
#pragma unroll
        for (int kk = 0; kk < 64; kk += 16) {
            uint32_t bh[4][2];
#pragma unroll
            for (int pr = 0; pr < 2; pr++) {
                uint32_t off = ((kk + bk) * BPAD + bn + pr * 16) * 2;
                uint32_t r0, r1, r2, r3;
                LDSM4T(r0, r1, r2, r3, Bb + off);
                bh[2 * pr][0] = r0; bh[2 * pr][1] = r1;
                bh[2 * pr + 1][0] = r2; bh[2 * pr + 1][1] = r3;
            }
#pragma unroll
            for (int mt = 0; mt < 4; mt++) {
                uint32_t ah[4];
                uint32_t off = ((am + mt * 16) * APAD + kk + akoff) * 2;
                LDSM4(ah, Ab + off);
#pragma unroll
                for (int nt = 0; nt < 4; nt++) {
                    MMA16816(acc[mt * 4 + nt], ah, bh[nt]);
                }
            }
        }
        __syncthreads();
        if (s + NSTAGE < NST) issue(s + NSTAGE);
    }

    // epilogue
    const int er = row0 + warp_m * 64 + (lane >> 2);
    const int ec = col0 + warp_n * 32 + (lane & 3) * 2;
#pragma unroll
    for (int mt = 0; mt < 4; mt++) {
#pragma unroll
        for (int nt = 0; nt < 4; nt++) {
            int c = ec + nt * 8;
            float b0 = bias[c], b1 = bias[c + 1];
#pragma unroll
            for (int hh = 0; hh < 2; hh++) {
                int r = er + mt * 16 + hh * 8;
                if (r < M) {
                    float v0 = acc[mt * 4 + nt][2 * hh] + b0;
                    float v1 = acc[mt * 4 + nt][2 * hh + 1] + b1;
                    if (C != nullptr)
                        *(float2*)(C + (size_t)r * DD + c) = make_float2(v0, v1);
                    if (Split != nullptr) {
                        float w0 = v0 > 0.f ? v0 : 0.01f * v0;
                        float w1 = v1 > 0.f ? v1 : 0.01f * v1;
                        __half2 hp = __floats2half2_rn(w0, w1);
                        Split[((size_t)r * DD + c) >> 1] = *(uint32_t*)&hp;
                    }
                }
            }
        }
    }
}

// ================= host orchestration =================
extern "C" void kernel_launch(void* const* d_in, const int* in_sizes, int n_in,
                              void* d_out, int out_size) {
    const float* x0 = (const float*)d_in[0];
    const float* x1 = (const float*)d_in[1];
    const int* ei01 = (const int*)d_in[2];
    const int* ei10 = (const int*)d_in[3];
    const int N0 = in_sizes[0] / DD;
    const int N1 = in_sizes[1] / DD;
    const int E01 = in_sizes[2] / 2;
    const int E10 = in_sizes[3] / 2;

    float *bp;
    fp16 *h0, *h1, *s0, *s1, *agga, *aggb, *Wph;
    int *csr01, *csr10, *rs01, *rs10, *cnt0, *cnt1, *part0, *part1, *bsum, *cur0, *cur1;
    cudaGetSymbolAddress((void**)&h0, g_h0);
    cudaGetSymbolAddress((void**)&h1, g_h1);
    cudaGetSymbolAddress((void**)&s0, g_s0);
    cudaGetSymbolAddress((void**)&s1, g_s1);
    cudaGetSymbolAddress((void**)&agga, g_agga);
    cudaGetSymbolAddress((void**)&aggb, g_aggb);
    cudaGetSymbolAddress((void**)&Wph, g_Wph);
    cudaGetSymbolAddress((void**)&bp, g_bp);
    cudaGetSymbolAddress((void**)&csr01, g_csr01);
    cudaGetSymbolAddress((void**)&csr10, g_csr10);
    cudaGetSymbolAddress((void**)&rs01, g_rs01);
    cudaGetSymbolAddress((void**)&rs10, g_rs10);
    cudaGetSymbolAddress((void**)&cnt0, g_cnt0);
    cudaGetSymbolAddress((void**)&cnt1, g_cnt1);
    cudaGetSymbolAddress((void**)&part0, g_part0);
    cudaGetSymbolAddress((void**)&part1, g_part1);
    cudaGetSymbolAddress((void**)&bsum, g_bsum);
    cudaGetSymbolAddress((void**)&cur0, g_cur0);
    cudaGetSymbolAddress((void**)&cur1, g_cur1);

    cudaFuncSetAttribute(gemm_fp16_k, cudaFuncAttributeMaxDynamicSharedMemorySize,
                         GEMM_SMEM);

    // ---- CSR build (both edge types batched) ----
    cudaMemsetAsync(cnt0, 0, (size_t)N1 * sizeof(int));
    cudaMemsetAsync(cnt1, 0, (size_t)N0 * sizeof(int));
    cudaMemsetAsync(cur0, 0, (size_t)N1 * sizeof(int));
    cudaMemsetAsync(cur1, 0, (size_t)N0 * sizeof(int));
    int Emax = (E01 > E10 ? E01 : E10);
    int Nmax = (N0 > N1 ? N0 : N1);
    int nb = (Nmax + 1023) / 1024;
    {
        dim3 gh((Emax + 255) / 256, 2);
        hist2_k<<<gh, 256>>>(ei01, E01, cnt0, ei10, E10, cnt1);
        dim3 gs1(nb, 2);
        scan1_k<<<gs1, 1024>>>(cnt0, cnt1, N1, N0, part0, part1, bsum);
        dim3 gs2(1, 2);
        scan2_k<<<gs2, 128>>>(bsum, nb);
        scan3_k<<<gs1, 1024>>>(part0, part1, bsum, rs01, rs10, N1, N0);
        fill2_k<<<gh, 256>>>(ei01, E01, rs01, cur0, csr01,
                             ei10, E10, rs10, cur1, csr10);
    }

    // ---- precombine weights (fp16 out) + biases ----
    PrePtrs pp;
    BCPtrs bc;
    for (int s = 0; s < 4; s++) {
        const float* Wn = (const float*)d_in[4 + 6 * s + 0];
        const float* bn = (const float*)d_in[4 + 6 * s + 1];
        const float* Ws_ = (const float*)d_in[4 + 6 * s + 2];
        const float* bs = (const float*)d_in[4 + 6 * s + 3];
        const float* Wu = (const float*)d_in[4 + 6 * s + 4];
        const float* bu = (const float*)d_in[4 + 6 * s + 5];
        pp.A[2 * s] = Wn;      pp.Bm[2 * s] = Wu;
        pp.C[2 * s] = Wph + (size_t)(2 * s) * DD * DD;
        pp.A[2 * s + 1] = Ws_; pp.Bm[2 * s + 1] = Wu + DD * DD;
        pp.C[2 * s + 1] = Wph + (size_t)(2 * s + 1) * DD * DD;
        bc.bn[s] = bn; bc.bs[s] = bs; bc.bu[s] = bu; bc.Wu[s] = Wu;
    }
    {
        dim3 gb(2, 4);
        biascomb_k<<<gb, 256>>>(bc, bp);
        dim3 g(4, 4, 8);
        gemm_pre_k<<<g, 256>>>(pp);
    }

    const int n40 = N0 * (DD / 4);
    const int n41 = N1 * (DD / 4);

    // ---- layer 1: self fp16 (one launch) + fused dual gather ----
    hhalf2_k<<<(n40 + n41 + 255) / 256, 256>>>((const float4*)x0, (uint2*)h0, n40,
                                               (const float4*)x1, (uint2*)h1, n41);
    {
        int totw = N1 + N0;
        gather2h_k<<<(totw + 7) / 8, 256>>>(h0, csr01, rs01, N1, (uint4*)agga,
                                            h1, csr10, rs10, N0, (uint4*)aggb);
    }
    // ---- layer 1 fused GEMM pair (fp16 splits only) ----
    {
        G2 g;
        g.A0[0] = agga; g.A1[0] = h1;
        g.W0[0] = Wph + (size_t)0 * DD * DD;
        g.W1[0] = Wph + (size_t)1 * DD * DD;
        g.bias[0] = bp + 0 * DD; g.C[0] = nullptr; g.Split[0] = (uint32_t*)s1; g.M[0] = N1;
        g.A0[1] = aggb; g.A1[1] = h0;
        g.W0[1] = Wph + (size_t)2 * DD * DD;
        g.W1[1] = Wph + (size_t)3 * DD * DD;
        g.bias[1] = bp + 1 * DD; g.C[1] = nullptr; g.Split[1] = (uint32_t*)s0; g.M[1] = N0;
        int mmax = (N0 > N1 ? N0 : N1);
        dim3 gr(4, (mmax + 127) / 128, 2);
        gemm_fp16_k<<<gr, 256, GEMM_SMEM>>>(g);
    }

    // ---- layer 2: fused dual gather over s0/s1 ----
    {
        int totw = N1 + N0;
        gather2h_k<<<(totw + 7) / 8, 256>>>(s0, csr01, rs01, N1, (uint4*)agga,
                                            s1, csr10, rs10, N0, (uint4*)aggb);
    }
    // ---- layer 2 fused GEMM pair -> fp32 outputs ----
    {
        float* out0 = (float*)d_out;
        float* out1 = out0 + (size_t)N0 * DD;
        G2 g;
        g.A0[0] = agga; g.A1[0] = s1;
        g.W0[0] = Wph + (size_t)4 * DD * DD;
        g.W1[0] = Wph + (size_t)5 * DD * DD;
        g.bias[0] = bp + 2 * DD; g.C[0] = out1; g.Split[0] = nullptr; g.M[0] = N1;
        g.A0[1] = aggb; g.A1[1] = s0;
        g.W0[1] = Wph + (size_t)6 * DD * DD;
        g.W1[1] = Wph + (size_t)7 * DD * DD;
        g.bias[1] = bp + 3 * DD; g.C[1] = out0; g.Split[1] = nullptr; g.M[1] = N0;
        int mmax = (N0 > N1 ? N0 : N1);
        dim3 gr(4, (mmax + 127) / 128, 2);
        gemm_fp16_k<<<gr, 256, GEMM_SMEM>>>(g);
    }
}